// round 1
// baseline (speedup 1.0000x reference)
#include <cuda_runtime.h>

#define B_ 2
#define V_ 20000
#define C_ 32
#define NB_ 12
#define KS_ 9
#define OUT_ 32
#define NNODES (B_*V_)
#define KDIM (KS_*C_)   /* 288 */

// Scratch (module-allocated, no runtime allocation)
__device__ float g_ux[NNODES * KS_];                 // 1.44 MB
__device__ float g_y[(size_t)NNODES * KDIM];         // 46 MB

// ---------------------------------------------------------------------------
// Kernel 1: ux[node][k] = sum_c x[node][c] * u[c][k]
// ---------------------------------------------------------------------------
__global__ void k_ux(const float* __restrict__ x, const float* __restrict__ u) {
    __shared__ float u_sm[C_ * KS_];
    for (int i = threadIdx.x; i < C_ * KS_; i += blockDim.x) u_sm[i] = u[i];
    __syncthreads();

    int node = blockIdx.x * blockDim.x + threadIdx.x;
    if (node >= NNODES) return;

    const float4* xr = reinterpret_cast<const float4*>(x + (size_t)node * C_);
    float acc[KS_];
#pragma unroll
    for (int k = 0; k < KS_; k++) acc[k] = 0.f;

#pragma unroll
    for (int c4 = 0; c4 < C_ / 4; c4++) {
        float4 v = xr[c4];
        float xs[4] = {v.x, v.y, v.z, v.w};
#pragma unroll
        for (int j = 0; j < 4; j++) {
            int c = c4 * 4 + j;
#pragma unroll
            for (int k = 0; k < KS_; k++)
                acc[k] = fmaf(xs[j], u_sm[c * KS_ + k], acc[k]);
        }
    }
    float* o = g_ux + (size_t)node * KS_;
#pragma unroll
    for (int k = 0; k < KS_; k++) o[k] = acc[k];
}

// ---------------------------------------------------------------------------
// Kernel 2: per node (warp): softmax attention weights q[n][k] (inv_deg folded),
//           then y[k][c] = sum_n q[n][k] * x_nb[n][c], written to g_y.
// ---------------------------------------------------------------------------
__global__ void __launch_bounds__(256) k_attn(const float* __restrict__ x,
                                              const float* __restrict__ cvec,
                                              const int* __restrict__ adj) {
    __shared__ float q_sm[8][NB_ * KS_];   // 8 warps/block
    const int warp = threadIdx.x >> 5;
    const int lane = threadIdx.x & 31;
    const int node = blockIdx.x * 8 + warp;
    if (node >= NNODES) return;
    const int b = node / V_;
    const int v = node - b * V_;

    // adj row (shared across batch dim)
    int a = (lane < NB_) ? adj[v * NB_ + lane] : 0;
    unsigned nz = __ballot_sync(0xffffffffu, a != 0);
    int deg = __popc(nz);
    float inv_deg = deg ? (1.f / (float)deg) : 0.f;

    const float* uxs = g_ux + (size_t)node * KS_;
    float* q = q_sm[warp];

    // Phase A: 108 exps spread over lanes
#pragma unroll
    for (int j = 0; j < 4; j++) {
        int p = lane + 32 * j;
        int n = p / KS_;               // <= 14, safe shfl index
        int k = p - n * KS_;
        int an = __shfl_sync(0xffffffffu, a, n & 31);
        if (p < NB_ * KS_) {
            float e = 0.f;
            if (an) {
                float un = g_ux[((size_t)b * V_ + (an - 1)) * KS_ + k];
                e = __expf(uxs[k] - un + cvec[k]);
            }
            q[p] = e;
        }
    }
    __syncwarp();

    // Row-normalize, fold inv_deg
    if (lane < NB_) {
        float s = 0.f;
#pragma unroll
        for (int k = 0; k < KS_; k++) s += q[lane * KS_ + k];
        float sc = (a && s > 0.f) ? (inv_deg / s) : 0.f;
#pragma unroll
        for (int k = 0; k < KS_; k++) q[lane * KS_ + k] *= sc;
    }
    __syncwarp();

    // Phase B: lane = channel c; accumulate y[k]
    float y[KS_];
#pragma unroll
    for (int k = 0; k < KS_; k++) y[k] = 0.f;

#pragma unroll
    for (int n = 0; n < NB_; n++) {
        int an = __shfl_sync(0xffffffffu, a, n);
        if (an == 0) continue;                       // uniform branch
        float xv = x[((size_t)b * V_ + (an - 1)) * C_ + lane];  // coalesced 128B
#pragma unroll
        for (int k = 0; k < KS_; k++)
            y[k] = fmaf(q[n * KS_ + k], xv, y[k]);   // q: smem broadcast
    }

    float* yo = g_y + (size_t)node * KDIM;
#pragma unroll
    for (int k = 0; k < KS_; k++)
        yo[k * C_ + lane] = y[k];                    // coalesced
}

// ---------------------------------------------------------------------------
// Kernel 3: out[row][o] = relu( sum_i Y[row][i] * W2[i][o] + bias[o] )
//   W2[(k*32+c)][o] = W[c][k][o];  M=40000, K=288, N=32.
//   Block: 256 threads, 128-row tile, 4x4 register microtile.
// ---------------------------------------------------------------------------
#define MB 128
#define KK 16
__global__ void __launch_bounds__(256) k_gemm(const float* __restrict__ W,
                                              const float* __restrict__ bias,
                                              float* __restrict__ out) {
    __shared__ __align__(16) float w_sm[KDIM * OUT_];   // 36 KB
    __shared__ float y_sm[MB][KK + 1];                  // 8.5 KB, pad -> no conflicts

    const int tid = threadIdx.x;

    // Load W transposed into smem: w_sm[(k*32+c)*32 + o] = W[c*288 + k*32 + o]
    for (int i = tid; i < KDIM * OUT_; i += 256) {
        int row = i >> 5;
        int o = i & 31;
        int c = row & 31;
        int k = row >> 5;
        w_sm[i] = W[c * KDIM + k * OUT_ + o];
    }

    const int row0 = blockIdx.x * MB;
    const int tr4 = (tid >> 3) * 4;   // row group (0..124)
    const int tc4 = (tid & 7) * 4;    // out group (0..28)

    float acc[4][4];
#pragma unroll
    for (int i = 0; i < 4; i++)
#pragma unroll
        for (int j = 0; j < 4; j++) acc[i][j] = 0.f;

    const int i_l = tid & (KK - 1);   // staging col 0..15
    const int r_l = tid >> 4;         // staging row 0..15

    for (int k0 = 0; k0 < KDIM; k0 += KK) {
        __syncthreads();
        // Stage Y tile: y_sm[r][i] = Y[row0+r][k0+i]
#pragma unroll
        for (int j = 0; j < MB / 16; j++) {
            int r = r_l + 16 * j;
            int grow = row0 + r;
            y_sm[r][i_l] = (grow < NNODES)
                               ? g_y[(size_t)grow * KDIM + k0 + i_l]
                               : 0.f;
        }
        __syncthreads();

#pragma unroll
        for (int kk = 0; kk < KK; kk++) {
            float4 wv = *reinterpret_cast<const float4*>(
                &w_sm[(k0 + kk) * OUT_ + tc4]);
            float y0 = y_sm[tr4 + 0][kk];
            float y1 = y_sm[tr4 + 1][kk];
            float y2 = y_sm[tr4 + 2][kk];
            float y3 = y_sm[tr4 + 3][kk];
            acc[0][0] = fmaf(y0, wv.x, acc[0][0]);
            acc[0][1] = fmaf(y0, wv.y, acc[0][1]);
            acc[0][2] = fmaf(y0, wv.z, acc[0][2]);
            acc[0][3] = fmaf(y0, wv.w, acc[0][3]);
            acc[1][0] = fmaf(y1, wv.x, acc[1][0]);
            acc[1][1] = fmaf(y1, wv.y, acc[1][1]);
            acc[1][2] = fmaf(y1, wv.z, acc[1][2]);
            acc[1][3] = fmaf(y1, wv.w, acc[1][3]);
            acc[2][0] = fmaf(y2, wv.x, acc[2][0]);
            acc[2][1] = fmaf(y2, wv.y, acc[2][1]);
            acc[2][2] = fmaf(y2, wv.z, acc[2][2]);
            acc[2][3] = fmaf(y2, wv.w, acc[2][3]);
            acc[3][0] = fmaf(y3, wv.x, acc[3][0]);
            acc[3][1] = fmaf(y3, wv.y, acc[3][1]);
            acc[3][2] = fmaf(y3, wv.z, acc[3][2]);
            acc[3][3] = fmaf(y3, wv.w, acc[3][3]);
        }
    }

    const float b0 = bias[tc4 + 0];
    const float b1 = bias[tc4 + 1];
    const float b2 = bias[tc4 + 2];
    const float b3 = bias[tc4 + 3];
#pragma unroll
    for (int i = 0; i < 4; i++) {
        int grow = row0 + tr4 + i;
        if (grow < NNODES) {
            float4 o4;
            o4.x = fmaxf(acc[i][0] + b0, 0.f);
            o4.y = fmaxf(acc[i][1] + b1, 0.f);
            o4.z = fmaxf(acc[i][2] + b2, 0.f);
            o4.w = fmaxf(acc[i][3] + b3, 0.f);
            *reinterpret_cast<float4*>(&out[(size_t)grow * OUT_ + tc4]) = o4;
        }
    }
}

// ---------------------------------------------------------------------------
// Inputs (metadata order): x, W, u, c, b, adj
// ---------------------------------------------------------------------------
extern "C" void kernel_launch(void* const* d_in, const int* in_sizes, int n_in,
                              void* d_out, int out_size) {
    const float* x    = (const float*)d_in[0];
    const float* W    = (const float*)d_in[1];
    const float* u    = (const float*)d_in[2];
    const float* cvec = (const float*)d_in[3];
    const float* bias = (const float*)d_in[4];
    const int*   adj  = (const int*)d_in[5];
    float* out = (float*)d_out;

    k_ux<<<(NNODES + 255) / 256, 256>>>(x, u);
    k_attn<<<(NNODES + 7) / 8, 256>>>(x, cvec, adj);
    k_gemm<<<(NNODES + MB - 1) / MB, 256>>>(W, bias, out);
}